// round 3
// baseline (speedup 1.0000x reference)
#include <cuda_runtime.h>
#include <math.h>

#define Bb   8
#define Tt   2048
#define Hh   2048
#define Nn   100000
#define Pp   512
#define TOPK 10
#define NCH  40            // topk stage-1 chunks per batch
#define CHSZ 2500          // Nn / NCH

typedef unsigned long long ull;

// ---------------- scratch (device globals; no allocations) ----------------
__device__ float g_part[Bb*32*Hh];      // partial T-sums: [b][chunk32][h]
__device__ float g_query[Bb*Hh];        // mean over T
__device__ float g_q[Bb*Pp];            // query @ Wq^T + bq
__device__ float g_sbk[Bb];             // q . bk
__device__ float g_qkD[Bb*Hh];          // qk warp-contiguous layout (64KB)
__device__ float g_scores[Bb*Nn];
__device__ float g_cval[Bb*NCH*TOPK];
__device__ int   g_cidx[Bb*NCH*TOPK];
__device__ float g_gi[Bb*2*Hh];
__device__ float g_gate[Bb*Hh];
__device__ float g_h1[Bb*Hh];
__device__ float g_mi[Bb*Hh];

// ---------------- f32x2 helpers ----------------
__device__ __forceinline__ ull pk2(float a, float b) {
    ull r; asm("mov.b64 %0,{%1,%2};" : "=l"(r) : "f"(a), "f"(b)); return r;
}
__device__ __forceinline__ void up2(ull v, float& a, float& b) {
    asm("mov.b64 {%0,%1},%2;" : "=f"(a), "=f"(b) : "l"(v));
}
__device__ __forceinline__ ull fma2(ull a, ull b, ull c) {
    ull d; asm("fma.rn.f32x2 %0,%1,%2,%3;" : "=l"(d) : "l"(a), "l"(b), "l"(c)); return d;
}

// ---------------- K0: partial sums over T ----------------
__global__ void __launch_bounds__(256) k_partial(const float* __restrict__ x) {
    int b = blockIdx.x >> 1, hseg = blockIdx.x & 1, chunk = blockIdx.y;   // 32 chunks x 64 t
    const float4* xp = (const float4*)x
        + ((size_t)(b*Tt + chunk*64) * Hh + hseg*1024) / 4 + threadIdx.x;
    float4 s = make_float4(0.f,0.f,0.f,0.f);
#pragma unroll 8
    for (int t = 0; t < 64; t++) {
        float4 v = __ldcs(xp + (size_t)t * (Hh/4));
        s.x += v.x; s.y += v.y; s.z += v.z; s.w += v.w;
    }
    ((float4*)g_part)[(b*32 + chunk)*(Hh/4) + hseg*256 + threadIdx.x] = s;
}

// ---------------- K1: query mean + q = query@Wq^T+bq + sbk (fused; 1 block/batch) ----------------
__global__ void __launch_bounds__(256) k_qsetup(const float* __restrict__ Wq,
                                                const float* __restrict__ bq,
                                                const float* __restrict__ bk) {
    __shared__ float4 qsm[512];       // query[b] as float4
    __shared__ float  sq[512];        // q[b]
    int b = blockIdx.x, tid = threadIdx.x;
    // query mean
    for (int h4 = tid; h4 < 512; h4 += 256) {
        float4 s = make_float4(0.f,0.f,0.f,0.f);
#pragma unroll
        for (int c = 0; c < 32; c++) {
            float4 v = ((const float4*)g_part)[(b*32 + c)*512 + h4];
            s.x += v.x; s.y += v.y; s.z += v.z; s.w += v.w;
        }
        const float inv = 1.0f / (float)Tt;
        s.x *= inv; s.y *= inv; s.z *= inv; s.w *= inv;
        qsm[h4] = s;
        ((float4*)g_query)[b*512 + h4] = s;
    }
    __syncthreads();
    // q projection: warp per output
    int lane = tid & 31, warp = tid >> 5;
    for (int o = warp; o < 512; o += 8) {
        const float4* w = (const float4*)Wq + (size_t)o*512;
        float s = 0.f;
        for (int i = lane; i < 512; i += 32) {
            float4 a = __ldg(w + i); float4 c = qsm[i];
            s += a.x*c.x + a.y*c.y + a.z*c.z + a.w*c.w;
        }
#pragma unroll
        for (int off = 16; off; off >>= 1) s += __shfl_xor_sync(0xffffffffu, s, off);
        if (lane == 0) sq[o] = s + bq[o];
    }
    __syncthreads();
    // write q + sbk
    for (int j = tid; j < 512; j += 256) g_q[b*Pp + j] = sq[j];
    if (warp == 0) {
        float s = 0.f;
        for (int i = lane; i < Pp; i += 32) s += sq[i] * bk[i];
#pragma unroll
        for (int off = 16; off; off >>= 1) s += __shfl_xor_sync(0xffffffffu, s, off);
        if (lane == 0) g_sbk[b] = s;
    }
}

// ---------------- K2: qk = q @ Wk, scattered directly to qkD layout ----------------
__global__ void __launch_bounds__(128) k_qk(const float* __restrict__ Wk) {
    __shared__ float qs[Bb*Pp];       // 16KB
    int tid = threadIdx.x;
    for (int j = tid; j < Bb*Pp; j += 128) qs[j] = g_q[j];
    __syncthreads();
    int h = blockIdx.x*128 + tid;
    float acc[8] = {0.f,0.f,0.f,0.f,0.f,0.f,0.f,0.f};
#pragma unroll 4
    for (int p = 0; p < 512; p++) {
        float w = __ldg(&Wk[(size_t)p*Hh + h]);
#pragma unroll
        for (int b = 0; b < 8; b++) acc[b] += qs[b*Pp + p] * w;
    }
    int c = h >> 2, i = c >> 5, l = c & 31, hh = h & 3;
#pragma unroll
    for (int b = 0; b < 8; b++)
        g_qkD[((i*8 + 2*hh + (b >> 2))*32 + l)*4 + (b & 3)] = acc[b];
}

// ---------------- K3: scores = (qk @ keys^T + sbk) * conf  (8 rows/warp) ----------------
__global__ void __launch_bounds__(128) k_scores(const float* __restrict__ keys,
                                                const float* __restrict__ conf) {
    const int lane = threadIdx.x & 31;
    const int warp = threadIdx.x >> 5;
    const int n0 = blockIdx.x*32 + warp*8;                 // 3125 blocks * 32 rows
    const float4* __restrict__ qkD4 = (const float4*)g_qkD;
    const float4* k0 = (const float4*)keys + (size_t)n0 * (Hh/4);
    // broadcast sbk once per thread (8 floats, L1/const-cached)
    float sbk[8];
#pragma unroll
    for (int bb = 0; bb < 8; bb++) sbk[bb] = __ldg(&g_sbk[bb]);
    ull acc[8][4];
#pragma unroll
    for (int r = 0; r < 8; r++)
#pragma unroll
        for (int j = 0; j < 4; j++) acc[r][j] = 0ull;
#pragma unroll 2
    for (int i = 0; i < 16; i++) {
        float4 kv[8];
#pragma unroll
        for (int r = 0; r < 8; r++)
            kv[r] = __ldcg(k0 + (size_t)r*(Hh/4) + i*32 + lane);
#pragma unroll
        for (int hh = 0; hh < 4; hh++) {
            ull kd[8];
#pragma unroll
            for (int r = 0; r < 8; r++) {
                float cc = (hh == 0) ? kv[r].x : (hh == 1) ? kv[r].y
                         : (hh == 2) ? kv[r].z : kv[r].w;
                kd[r] = pk2(cc, cc);
            }
#pragma unroll
            for (int s = 0; s < 2; s++) {
                float4 qv = __ldg(&qkD4[(i*8 + hh*2 + s)*32 + lane]);
                ull qlo = pk2(qv.x, qv.y), qhi = pk2(qv.z, qv.w);
#pragma unroll
                for (int r = 0; r < 8; r++) {
                    acc[r][2*s]   = fma2(kd[r], qlo, acc[r][2*s]);
                    acc[r][2*s+1] = fma2(kd[r], qhi, acc[r][2*s+1]);
                }
            }
        }
    }
#pragma unroll
    for (int r = 0; r < 8; r++) {
        float a[8];
#pragma unroll
        for (int j = 0; j < 4; j++) up2(acc[r][j], a[2*j], a[2*j+1]);
#pragma unroll
        for (int off = 16; off; off >>= 1)
#pragma unroll
            for (int bb = 0; bb < 8; bb++)
                a[bb] += __shfl_xor_sync(0xffffffffu, a[bb], off);
        if (lane == 0) {
            int n = n0 + r;
            float cf = __ldg(&conf[n]);
#pragma unroll
            for (int bb = 0; bb < 8; bb++)
                g_scores[(size_t)bb*Nn + n] = (a[bb] + sbk[bb]) * cf;
        }
    }
}

// ---------------- K4: top-k stage 1 (block-local top-10 per 2500-chunk) ----------------
__global__ void __launch_bounds__(256) k_topk1() {
    int b = blockIdx.y, c = blockIdx.x, tid = threadIdx.x;
    int nbase = c * CHSZ;
    float v[TOPK]; int ix[TOPK];
#pragma unroll
    for (int j = 0; j < TOPK; j++) { v[j] = -3.4e38f; ix[j] = 0x7fffffff; }
    const float* sc = g_scores + (size_t)b*Nn + nbase;
    for (int n = tid; n < CHSZ; n += 256) {
        float s = sc[n];
        if (s > v[TOPK-1]) {
            v[TOPK-1] = s; ix[TOPK-1] = nbase + n;
#pragma unroll
            for (int j = TOPK-1; j > 0; j--) {
                bool sw = (v[j] > v[j-1]) || (v[j] == v[j-1] && ix[j] < ix[j-1]);
                if (sw) {
                    float tv = v[j]; v[j] = v[j-1]; v[j-1] = tv;
                    int   ti = ix[j]; ix[j] = ix[j-1]; ix[j-1] = ti;
                }
            }
        }
    }
    __shared__ float sv[256*TOPK];
    __shared__ int   si[256*TOPK];
    __shared__ float rv[256]; __shared__ int ri[256]; __shared__ int rp[256];
#pragma unroll
    for (int j = 0; j < TOPK; j++) { sv[tid*TOPK + j] = v[j]; si[tid*TOPK + j] = ix[j]; }
    __syncthreads();
    for (int k = 0; k < TOPK; k++) {
        float bv = -3.4e38f; int bi = 0x7fffffff, bp = 0;
        for (int j = tid; j < 256*TOPK; j += 256) {
            float cv = sv[j]; int ci = si[j];
            if (cv > bv || (cv == bv && ci < bi)) { bv = cv; bi = ci; bp = j; }
        }
        rv[tid] = bv; ri[tid] = bi; rp[tid] = bp;
        __syncthreads();
        for (int st = 128; st > 0; st >>= 1) {
            if (tid < st) {
                float cv = rv[tid+st]; int ci = ri[tid+st];
                if (cv > rv[tid] || (cv == rv[tid] && ci < ri[tid])) {
                    rv[tid] = cv; ri[tid] = ci; rp[tid] = rp[tid+st];
                }
            }
            __syncthreads();
        }
        if (tid == 0) {
            g_cval[(b*NCH + c)*TOPK + k] = rv[0];
            g_cidx[(b*NCH + c)*TOPK + k] = ri[0];
            sv[rp[0]] = -3.4e38f;
        }
        __syncthreads();
    }
}

// ---------------- K5: top-k stage 2 + gather mean + gate_input (fused) ----------------
__global__ void __launch_bounds__(256) k_topk2gi(const float* __restrict__ keys) {
    int b = blockIdx.x, tid = threadIdx.x;
    const int NC = NCH*TOPK;   // 400
    __shared__ float cv[NC]; __shared__ int ci[NC];
    __shared__ float rv[256]; __shared__ int ri[256]; __shared__ int rp[256];
    __shared__ int topi[TOPK];
    for (int j = tid; j < NC; j += 256) {
        cv[j] = g_cval[b*NC + j]; ci[j] = g_cidx[b*NC + j];
    }
    __syncthreads();
    for (int k = 0; k < TOPK; k++) {
        float bv = -3.4e38f; int bi = 0x7fffffff, bp = 0;
        for (int j = tid; j < NC; j += 256) {
            float vv = cv[j]; int ii = ci[j];
            if (vv > bv || (vv == bv && ii < bi)) { bv = vv; bi = ii; bp = j; }
        }
        rv[tid] = bv; ri[tid] = bi; rp[tid] = bp;
        __syncthreads();
        for (int st = 128; st > 0; st >>= 1) {
            if (tid < st) {
                float vv = rv[tid+st]; int ii = ri[tid+st];
                if (vv > rv[tid] || (vv == rv[tid] && ii < ri[tid])) {
                    rv[tid] = vv; ri[tid] = ii; rp[tid] = rp[tid+st];
                }
            }
            __syncthreads();
        }
        if (tid == 0) { topi[k] = ri[0]; cv[rp[0]] = -3.4e38f; }
        __syncthreads();
    }
    // gate_input = concat(query, mean of retrieved keys)
    int idx[TOPK];
#pragma unroll
    for (int j = 0; j < TOPK; j++) idx[j] = topi[j];
    for (int h4 = tid; h4 < 512; h4 += 256) {
        ((float4*)g_gi)[b*1024 + h4] = ((const float4*)g_query)[b*512 + h4];
        float4 s = make_float4(0.f,0.f,0.f,0.f);
#pragma unroll
        for (int j = 0; j < TOPK; j++) {
            float4 kv = __ldg((const float4*)keys + (size_t)idx[j]*(Hh/4) + h4);
            s.x += kv.x; s.y += kv.y; s.z += kv.z; s.w += kv.w;
        }
        const float inv = 1.0f / (float)TOPK;
        s.x *= inv; s.y *= inv; s.z *= inv; s.w *= inv;
        ((float4*)g_gi)[b*1024 + 512 + h4] = s;
    }
}

// ---------------- K6: gate = sigmoid(gi@Wg^T+bg), h1 = gelu(gi@Wm1^T+bm1) ----------------
__global__ void __launch_bounds__(256) k_mlp1(const float* __restrict__ Wg,
                                              const float* __restrict__ bg,
                                              const float* __restrict__ Wm1,
                                              const float* __restrict__ bm1) {
    int lane = threadIdx.x & 31, warp = threadIdx.x >> 5;
    int wg = blockIdx.x*8 + warp;
    int which = wg >> 11, o = wg & 2047;
    const float4* W = (const float4*)(which ? Wm1 : Wg) + (size_t)o*1024;
    float acc[8] = {0.f,0.f,0.f,0.f,0.f,0.f,0.f,0.f};
    for (int i = lane; i < 1024; i += 32) {
        float4 w = __ldcs(W + i);
#pragma unroll
        for (int b = 0; b < 8; b++) {
            float4 g = __ldg((const float4*)g_gi + b*1024 + i);
            acc[b] += w.x*g.x + w.y*g.y + w.z*g.z + w.w*g.w;
        }
    }
#pragma unroll
    for (int off = 16; off; off >>= 1)
#pragma unroll
        for (int b = 0; b < 8; b++) acc[b] += __shfl_xor_sync(0xffffffffu, acc[b], off);
    if (lane == 0) {
        float bias = which ? bm1[o] : bg[o];
#pragma unroll
        for (int b = 0; b < 8; b++) {
            float z = acc[b] + bias;
            if (which) g_h1[b*Hh + o] = 0.5f*z*(1.0f + erff(z*0.70710678118654752440f));
            else       g_gate[b*Hh + o] = 1.0f / (1.0f + expf(-z));
        }
    }
}

// ---------------- K7: mem_integrated = h1 @ Wm2^T + bm2 ----------------
__global__ void __launch_bounds__(256) k_mi(const float* __restrict__ Wm2,
                                            const float* __restrict__ bm2) {
    int lane = threadIdx.x & 31, warp = threadIdx.x >> 5;
    int o = blockIdx.x*8 + warp;
    const float4* W = (const float4*)Wm2 + (size_t)o*512;
    float acc[8] = {0.f,0.f,0.f,0.f,0.f,0.f,0.f,0.f};
    for (int i = lane; i < 512; i += 32) {
        float4 w = __ldcs(W + i);
#pragma unroll
        for (int b = 0; b < 8; b++) {
            float4 g = __ldg((const float4*)g_h1 + b*512 + i);
            acc[b] += w.x*g.x + w.y*g.y + w.z*g.z + w.w*g.w;
        }
    }
#pragma unroll
    for (int off = 16; off; off >>= 1)
#pragma unroll
        for (int b = 0; b < 8; b++) acc[b] += __shfl_xor_sync(0xffffffffu, acc[b], off);
    if (lane == 0) {
        float bias = bm2[o];
#pragma unroll
        for (int b = 0; b < 8; b++) g_mi[b*Hh + o] = acc[b] + bias;
    }
}

// ---------------- K8: y = x + gate*mi; LayerNorm over H ----------------
__global__ void __launch_bounds__(256) k_final(const float* __restrict__ x,
                                               const float* __restrict__ gamma,
                                               const float* __restrict__ beta,
                                               float* __restrict__ out) {
    int row = blockIdx.x;            // b*T + t
    int b = row >> 11;
    const float4* xr = (const float4*)x + (size_t)row*512;
    float4* orow = (float4*)out + (size_t)row*512;
    int i0 = threadIdx.x, i1 = threadIdx.x + 256;
    float4 x0 = __ldcs(xr + i0), x1 = __ldcs(xr + i1);
    float4 ga = __ldg((const float4*)g_gate + b*512 + i0);
    float4 gb = __ldg((const float4*)g_gate + b*512 + i1);
    float4 ma = __ldg((const float4*)g_mi   + b*512 + i0);
    float4 mb = __ldg((const float4*)g_mi   + b*512 + i1);
    float4 y0, y1;
    y0.x = x0.x + ga.x*ma.x; y0.y = x0.y + ga.y*ma.y;
    y0.z = x0.z + ga.z*ma.z; y0.w = x0.w + ga.w*ma.w;
    y1.x = x1.x + gb.x*mb.x; y1.y = x1.y + gb.y*mb.y;
    y1.z = x1.z + gb.z*mb.z; y1.w = x1.w + gb.w*mb.w;
    float s  = y0.x + y0.y + y0.z + y0.w + y1.x + y1.y + y1.z + y1.w;
    float ss = y0.x*y0.x + y0.y*y0.y + y0.z*y0.z + y0.w*y0.w
             + y1.x*y1.x + y1.y*y1.y + y1.z*y1.z + y1.w*y1.w;
#pragma unroll
    for (int off = 16; off; off >>= 1) {
        s  += __shfl_xor_sync(0xffffffffu, s,  off);
        ss += __shfl_xor_sync(0xffffffffu, ss, off);
    }
    __shared__ float sh[16];
    int lane = threadIdx.x & 31, warp = threadIdx.x >> 5;
    if (lane == 0) { sh[warp] = s; sh[8 + warp] = ss; }
    __syncthreads();
    if (threadIdx.x < 32) {
        float a = (lane < 8) ? sh[lane] : 0.f;
        float c = (lane < 8) ? sh[8 + lane] : 0.f;
#pragma unroll
        for (int off = 4; off; off >>= 1) {
            a += __shfl_xor_sync(0xffffffffu, a, off);
            c += __shfl_xor_sync(0xffffffffu, c, off);
        }
        if (lane == 0) { sh[0] = a; sh[1] = c; }
    }
    __syncthreads();
    float mu  = sh[0] * (1.0f/2048.0f);
    float var = sh[1] * (1.0f/2048.0f) - mu*mu;
    float rstd = rsqrtf(var + 1e-5f);
    float4 gm0 = __ldg((const float4*)gamma + i0), gm1 = __ldg((const float4*)gamma + i1);
    float4 be0 = __ldg((const float4*)beta  + i0), be1 = __ldg((const float4*)beta  + i1);
    float4 o0, o1;
    o0.x = (y0.x - mu)*rstd*gm0.x + be0.x; o0.y = (y0.y - mu)*rstd*gm0.y + be0.y;
    o0.z = (y0.z - mu)*rstd*gm0.z + be0.z; o0.w = (y0.w - mu)*rstd*gm0.w + be0.w;
    o1.x = (y1.x - mu)*rstd*gm1.x + be1.x; o1.y = (y1.y - mu)*rstd*gm1.y + be1.y;
    o1.z = (y1.z - mu)*rstd*gm1.z + be1.z; o1.w = (y1.w - mu)*rstd*gm1.w + be1.w;
    orow[i0] = o0; orow[i1] = o1;
}

// ---------------- launch ----------------
extern "C" void kernel_launch(void* const* d_in, const int* in_sizes, int n_in,
                              void* d_out, int out_size) {
    const float* x     = (const float*)d_in[0];
    const float* keys  = (const float*)d_in[1];
    const float* conf  = (const float*)d_in[2];
    const float* Wq    = (const float*)d_in[3];
    const float* bq    = (const float*)d_in[4];
    const float* Wk    = (const float*)d_in[5];
    const float* bk    = (const float*)d_in[6];
    const float* Wg    = (const float*)d_in[7];
    const float* bg    = (const float*)d_in[8];
    const float* Wm1   = (const float*)d_in[9];
    const float* bm1   = (const float*)d_in[10];
    const float* Wm2   = (const float*)d_in[11];
    const float* bm2   = (const float*)d_in[12];
    const float* gamma = (const float*)d_in[13];
    const float* beta  = (const float*)d_in[14];
    float* out = (float*)d_out;

    k_partial <<<dim3(16,32), 256>>>(x);          // launch 0
    k_qsetup  <<<8, 256>>>(Wq, bq, bk);           // launch 1
    k_qk      <<<16, 128>>>(Wk);                  // launch 2
    k_scores  <<<3125, 128>>>(keys, conf);        // launch 3  (ncu slot)
    k_topk1   <<<dim3(NCH, Bb), 256>>>();         // launch 4
    k_topk2gi <<<8, 256>>>(keys);                 // launch 5
    k_mlp1    <<<512, 256>>>(Wg, bg, Wm1, bm1);   // launch 6
    k_mi      <<<256, 256>>>(Wm2, bm2);           // launch 7
    k_final   <<<16384, 256>>>(x, gamma, beta, out); // launch 8
}

// round 9
// speedup vs baseline: 1.8044x; 1.8044x over previous
#include <cuda_runtime.h>
#include <math.h>

#define Bb   8
#define Tt   2048
#define Hh   2048
#define Nn   100000
#define Pp   512
#define TOPK 10
#define NCH  40
#define CHSZ 2500

typedef unsigned long long ull;

// ---------------- scratch ----------------
__device__ float g_part[Bb*32*Hh];
__device__ float g_query[Bb*Hh];
__device__ float g_q[Bb*Pp];
__device__ float g_sbk[Bb];
__device__ float g_qkD[Bb*Hh];
__device__ float g_scores[Bb*Nn];
__device__ float g_cval[Bb*NCH*TOPK];
__device__ int   g_cidx[Bb*NCH*TOPK];
__device__ float g_gi[Bb*2*Hh];
__device__ float g_gate[Bb*Hh];
__device__ float g_h1[Bb*Hh];
__device__ float g_mi[Bb*Hh];

// ---------------- f32x2 helpers ----------------
__device__ __forceinline__ ull pk2(float a, float b) {
    ull r; asm("mov.b64 %0,{%1,%2};" : "=l"(r) : "f"(a), "f"(b)); return r;
}
__device__ __forceinline__ void up2(ull v, float& a, float& b) {
    asm("mov.b64 {%0,%1},%2;" : "=f"(a), "=f"(b) : "l"(v));
}
__device__ __forceinline__ ull fma2(ull a, ull b, ull c) {
    ull d; asm("fma.rn.f32x2 %0,%1,%2,%3;" : "=l"(d) : "l"(a), "l"(b), "l"(c)); return d;
}

// ---------------- K0: partial sums over T ----------------
__global__ void __launch_bounds__(256) k_partial(const float* __restrict__ x) {
    int b = blockIdx.x >> 1, hseg = blockIdx.x & 1, chunk = blockIdx.y;
    const float4* xp = (const float4*)x
        + ((size_t)(b*Tt + chunk*64) * Hh + hseg*1024) / 4 + threadIdx.x;
    float4 s = make_float4(0.f,0.f,0.f,0.f);
#pragma unroll 8
    for (int t = 0; t < 64; t++) {
        float4 v = __ldcs(xp + (size_t)t * (Hh/4));
        s.x += v.x; s.y += v.y; s.z += v.z; s.w += v.w;
    }
    ((float4*)g_part)[(b*32 + chunk)*(Hh/4) + hseg*256 + threadIdx.x] = s;
}

// ---------------- K1: query mean (16 blocks) ----------------
__global__ void __launch_bounds__(256) k_qmean() {
    int id = blockIdx.x*256 + threadIdx.x;   // 4096 = B*H/4
    int b = id >> 9, h4 = id & 511;
    float4 s = make_float4(0.f,0.f,0.f,0.f);
#pragma unroll
    for (int c = 0; c < 32; c++) {
        float4 v = ((const float4*)g_part)[(b*32 + c)*512 + h4];
        s.x += v.x; s.y += v.y; s.z += v.z; s.w += v.w;
    }
    const float inv = 1.0f / (float)Tt;
    s.x *= inv; s.y *= inv; s.z *= inv; s.w *= inv;
    ((float4*)g_query)[b*512 + h4] = s;
}

// ---------------- K2: q = query @ Wq^T + bq  (64 blocks, warp per output, all batches) ----------------
__global__ void __launch_bounds__(256) k_qproj(const float* __restrict__ Wq,
                                               const float* __restrict__ bq) {
    int lane = threadIdx.x & 31, warp = threadIdx.x >> 5;
    int o = blockIdx.x*8 + warp;
    const float4* w  = (const float4*)Wq + (size_t)o*512;
    const float4* gq = (const float4*)g_query;
    float acc[8] = {0.f,0.f,0.f,0.f,0.f,0.f,0.f,0.f};
#pragma unroll 4
    for (int j = 0; j < 16; j++) {
        int i = j*32 + lane;
        float4 a = __ldg(w + i);
#pragma unroll
        for (int b = 0; b < 8; b++) {
            float4 c = __ldg(gq + b*512 + i);
            acc[b] += a.x*c.x + a.y*c.y + a.z*c.z + a.w*c.w;
        }
    }
#pragma unroll
    for (int off = 16; off; off >>= 1)
#pragma unroll
        for (int b = 0; b < 8; b++) acc[b] += __shfl_xor_sync(0xffffffffu, acc[b], off);
    if (lane == 0) {
        float bias = __ldg(&bq[o]);
#pragma unroll
        for (int b = 0; b < 8; b++) g_q[b*Pp + o] = acc[b] + bias;
    }
}

// ---------------- K3: qk = q @ Wk → qkD layout; sbk fused (64 blocks) ----------------
__global__ void __launch_bounds__(256) k_qk(const float* __restrict__ Wk,
                                            const float* __restrict__ bk) {
    __shared__ float qsm[Pp*Bb];        // [p][b] packed, 16KB
    __shared__ float red[8*32*8];       // [ps][lh][b], 8KB
    int tid = threadIdx.x;
    for (int j = tid; j < Bb*Pp; j += 256) {
        int b = j >> 9, p = j & 511;
        qsm[p*8 + b] = g_q[j];
    }
    __syncthreads();
    int lane = tid & 31, ps = tid >> 5;
    // sbk: block 0 only, warp ps computes batch ps
    if (blockIdx.x == 0) {
        float s = 0.f;
        for (int p = lane; p < Pp; p += 32) s += qsm[p*8 + ps] * __ldg(&bk[p]);
#pragma unroll
        for (int off = 16; off; off >>= 1) s += __shfl_xor_sync(0xffffffffu, s, off);
        if (lane == 0) g_sbk[ps] = s;
    }
    int h = blockIdx.x*32 + lane;
    int p0 = ps*64;
    float acc[8] = {0.f,0.f,0.f,0.f,0.f,0.f,0.f,0.f};
#pragma unroll 8
    for (int j = 0; j < 64; j++) {
        int p = p0 + j;
        float w = __ldg(&Wk[(size_t)p*Hh + h]);
        const float4* qp = (const float4*)&qsm[p*8];
        float4 qA = qp[0], qB = qp[1];
        acc[0] += qA.x*w; acc[1] += qA.y*w; acc[2] += qA.z*w; acc[3] += qA.w*w;
        acc[4] += qB.x*w; acc[5] += qB.y*w; acc[6] += qB.z*w; acc[7] += qB.w*w;
    }
#pragma unroll
    for (int b = 0; b < 8; b++) red[(ps*32 + lane)*8 + b] = acc[b];
    __syncthreads();
    // reduce over ps: thread = (lh, b)
    int lh = tid >> 3, b = tid & 7;
    float s = 0.f;
#pragma unroll
    for (int p2 = 0; p2 < 8; p2++) s += red[(p2*32 + lh)*8 + b];
    int hg = blockIdx.x*32 + lh;
    int c = hg >> 2, i = c >> 5, l = c & 31, hh = hg & 3;
    g_qkD[((i*8 + 2*hh + (b >> 2))*32 + l)*4 + (b & 3)] = s;
}

// ---------------- K4: scores (software-pipelined, 8 rows/warp) ----------------
__device__ __forceinline__ void score_step(const float4 kv[8], const float4* __restrict__ qkD4,
                                           int i, int lane, ull acc[8][4]) {
#pragma unroll
    for (int hh = 0; hh < 4; hh++) {
        ull kd[8];
#pragma unroll
        for (int r = 0; r < 8; r++) {
            float cc = (hh == 0) ? kv[r].x : (hh == 1) ? kv[r].y
                     : (hh == 2) ? kv[r].z : kv[r].w;
            kd[r] = pk2(cc, cc);
        }
#pragma unroll
        for (int s = 0; s < 2; s++) {
            float4 qv = __ldg(&qkD4[(i*8 + hh*2 + s)*32 + lane]);
            ull qlo = pk2(qv.x, qv.y), qhi = pk2(qv.z, qv.w);
#pragma unroll
            for (int r = 0; r < 8; r++) {
                acc[r][2*s]   = fma2(kd[r], qlo, acc[r][2*s]);
                acc[r][2*s+1] = fma2(kd[r], qhi, acc[r][2*s+1]);
            }
        }
    }
}

__global__ void __launch_bounds__(128) k_scores(const float* __restrict__ keys,
                                                const float* __restrict__ conf) {
    const int lane = threadIdx.x & 31;
    const int warp = threadIdx.x >> 5;
    const int n0 = blockIdx.x*32 + warp*8;
    const float4* __restrict__ qkD4 = (const float4*)g_qkD;
    const float4* k0 = (const float4*)keys + (size_t)n0 * (Hh/4);
    float sbk[8];
#pragma unroll
    for (int bb = 0; bb < 8; bb++) sbk[bb] = __ldg(&g_sbk[bb]);
    ull acc[8][4];
#pragma unroll
    for (int r = 0; r < 8; r++)
#pragma unroll
        for (int j = 0; j < 4; j++) acc[r][j] = 0ull;
    float4 kvA[8], kvB[8];
#pragma unroll
    for (int r = 0; r < 8; r++)
        kvA[r] = __ldcg(k0 + (size_t)r*(Hh/4) + lane);            // i=0
    for (int i = 0; i < 16; i += 2) {
#pragma unroll
        for (int r = 0; r < 8; r++)                               // prefetch i+1
            kvB[r] = __ldcg(k0 + (size_t)r*(Hh/4) + (i+1)*32 + lane);
        score_step(kvA, qkD4, i, lane, acc);
        if (i + 2 < 16) {
#pragma unroll
            for (int r = 0; r < 8; r++)                           // prefetch i+2
                kvA[r] = __ldcg(k0 + (size_t)r*(Hh/4) + (i+2)*32 + lane);
        }
        score_step(kvB, qkD4, i+1, lane, acc);
    }
#pragma unroll
    for (int r = 0; r < 8; r++) {
        float a[8];
#pragma unroll
        for (int j = 0; j < 4; j++) up2(acc[r][j], a[2*j], a[2*j+1]);
#pragma unroll
        for (int off = 16; off; off >>= 1)
#pragma unroll
            for (int bb = 0; bb < 8; bb++)
                a[bb] += __shfl_xor_sync(0xffffffffu, a[bb], off);
        if (lane == 0) {
            int n = n0 + r;
            float cf = __ldg(&conf[n]);
#pragma unroll
            for (int bb = 0; bb < 8; bb++)
                g_scores[(size_t)bb*Nn + n] = (a[bb] + sbk[bb]) * cf;
        }
    }
}

// ---------------- K5: top-k stage 1 ----------------
__global__ void __launch_bounds__(256) k_topk1() {
    int b = blockIdx.y, c = blockIdx.x, tid = threadIdx.x;
    int nbase = c * CHSZ;
    float v[TOPK]; int ix[TOPK];
#pragma unroll
    for (int j = 0; j < TOPK; j++) { v[j] = -3.4e38f; ix[j] = 0x7fffffff; }
    const float* sc = g_scores + (size_t)b*Nn + nbase;
    for (int n = tid; n < CHSZ; n += 256) {
        float s = sc[n];
        if (s > v[TOPK-1]) {
            v[TOPK-1] = s; ix[TOPK-1] = nbase + n;
#pragma unroll
            for (int j = TOPK-1; j > 0; j--) {
                bool sw = (v[j] > v[j-1]) || (v[j] == v[j-1] && ix[j] < ix[j-1]);
                if (sw) {
                    float tv = v[j]; v[j] = v[j-1]; v[j-1] = tv;
                    int   ti = ix[j]; ix[j] = ix[j-1]; ix[j-1] = ti;
                }
            }
        }
    }
    __shared__ float sv[256*TOPK];
    __shared__ int   si[256*TOPK];
    __shared__ float rv[256]; __shared__ int ri[256]; __shared__ int rp[256];
#pragma unroll
    for (int j = 0; j < TOPK; j++) { sv[tid*TOPK + j] = v[j]; si[tid*TOPK + j] = ix[j]; }
    __syncthreads();
    for (int k = 0; k < TOPK; k++) {
        float bv = -3.4e38f; int bi = 0x7fffffff, bp = 0;
        for (int j = tid; j < 256*TOPK; j += 256) {
            float cv = sv[j]; int ci = si[j];
            if (cv > bv || (cv == bv && ci < bi)) { bv = cv; bi = ci; bp = j; }
        }
        rv[tid] = bv; ri[tid] = bi; rp[tid] = bp;
        __syncthreads();
        for (int st = 128; st > 0; st >>= 1) {
            if (tid < st) {
                float cv = rv[tid+st]; int ci = ri[tid+st];
                if (cv > rv[tid] || (cv == rv[tid] && ci < ri[tid])) {
                    rv[tid] = cv; ri[tid] = ci; rp[tid] = rp[tid+st];
                }
            }
            __syncthreads();
        }
        if (tid == 0) {
            g_cval[(b*NCH + c)*TOPK + k] = rv[0];
            g_cidx[(b*NCH + c)*TOPK + k] = ri[0];
            sv[rp[0]] = -3.4e38f;
        }
        __syncthreads();
    }
}

// ---------------- K6: top-k stage 2 + gather mean + gate_input ----------------
__global__ void __launch_bounds__(256) k_topk2gi(const float* __restrict__ keys) {
    int b = blockIdx.x, tid = threadIdx.x;
    const int NC = NCH*TOPK;
    __shared__ float cv[NC]; __shared__ int ci[NC];
    __shared__ float rv[256]; __shared__ int ri[256]; __shared__ int rp[256];
    __shared__ int topi[TOPK];
    for (int j = tid; j < NC; j += 256) {
        cv[j] = g_cval[b*NC + j]; ci[j] = g_cidx[b*NC + j];
    }
    __syncthreads();
    for (int k = 0; k < TOPK; k++) {
        float bv = -3.4e38f; int bi = 0x7fffffff, bp = 0;
        for (int j = tid; j < NC; j += 256) {
            float vv = cv[j]; int ii = ci[j];
            if (vv > bv || (vv == bv && ii < bi)) { bv = vv; bi = ii; bp = j; }
        }
        rv[tid] = bv; ri[tid] = bi; rp[tid] = bp;
        __syncthreads();
        for (int st = 128; st > 0; st >>= 1) {
            if (tid < st) {
                float vv = rv[tid+st]; int ii = ri[tid+st];
                if (vv > rv[tid] || (vv == rv[tid] && ii < ri[tid])) {
                    rv[tid] = vv; ri[tid] = ii; rp[tid] = rp[tid+st];
                }
            }
            __syncthreads();
        }
        if (tid == 0) { topi[k] = ri[0]; cv[rp[0]] = -3.4e38f; }
        __syncthreads();
    }
    int idx[TOPK];
#pragma unroll
    for (int j = 0; j < TOPK; j++) idx[j] = topi[j];
    for (int h4 = tid; h4 < 512; h4 += 256) {
        ((float4*)g_gi)[b*1024 + h4] = ((const float4*)g_query)[b*512 + h4];
        float4 s = make_float4(0.f,0.f,0.f,0.f);
#pragma unroll
        for (int j = 0; j < TOPK; j++) {
            float4 kv = __ldg((const float4*)keys + (size_t)idx[j]*(Hh/4) + h4);
            s.x += kv.x; s.y += kv.y; s.z += kv.z; s.w += kv.w;
        }
        const float inv = 1.0f / (float)TOPK;
        s.x *= inv; s.y *= inv; s.z *= inv; s.w *= inv;
        ((float4*)g_gi)[b*1024 + 512 + h4] = s;
    }
}

// ---------------- K7: gate/h1 ----------------
__global__ void __launch_bounds__(256) k_mlp1(const float* __restrict__ Wg,
                                              const float* __restrict__ bg,
                                              const float* __restrict__ Wm1,
                                              const float* __restrict__ bm1) {
    int lane = threadIdx.x & 31, warp = threadIdx.x >> 5;
    int wg = blockIdx.x*8 + warp;
    int which = wg >> 11, o = wg & 2047;
    const float4* W = (const float4*)(which ? Wm1 : Wg) + (size_t)o*1024;
    float acc[8] = {0.f,0.f,0.f,0.f,0.f,0.f,0.f,0.f};
    for (int i = lane; i < 1024; i += 32) {
        float4 w = __ldcs(W + i);
#pragma unroll
        for (int b = 0; b < 8; b++) {
            float4 g = __ldg((const float4*)g_gi + b*1024 + i);
            acc[b] += w.x*g.x + w.y*g.y + w.z*g.z + w.w*g.w;
        }
    }
#pragma unroll
    for (int off = 16; off; off >>= 1)
#pragma unroll
        for (int b = 0; b < 8; b++) acc[b] += __shfl_xor_sync(0xffffffffu, acc[b], off);
    if (lane == 0) {
        float bias = which ? bm1[o] : bg[o];
#pragma unroll
        for (int b = 0; b < 8; b++) {
            float z = acc[b] + bias;
            if (which) g_h1[b*Hh + o] = 0.5f*z*(1.0f + erff(z*0.70710678118654752440f));
            else       g_gate[b*Hh + o] = 1.0f / (1.0f + expf(-z));
        }
    }
}

// ---------------- K8: mem_integrated ----------------
__global__ void __launch_bounds__(256) k_mi(const float* __restrict__ Wm2,
                                            const float* __restrict__ bm2) {
    int lane = threadIdx.x & 31, warp = threadIdx.x >> 5;
    int o = blockIdx.x*8 + warp;
    const float4* W = (const float4*)Wm2 + (size_t)o*512;
    float acc[8] = {0.f,0.f,0.f,0.f,0.f,0.f,0.f,0.f};
    for (int i = lane; i < 512; i += 32) {
        float4 w = __ldcs(W + i);
#pragma unroll
        for (int b = 0; b < 8; b++) {
            float4 g = __ldg((const float4*)g_h1 + b*512 + i);
            acc[b] += w.x*g.x + w.y*g.y + w.z*g.z + w.w*g.w;
        }
    }
#pragma unroll
    for (int off = 16; off; off >>= 1)
#pragma unroll
        for (int b = 0; b < 8; b++) acc[b] += __shfl_xor_sync(0xffffffffu, acc[b], off);
    if (lane == 0) {
        float bias = bm2[o];
#pragma unroll
        for (int b = 0; b < 8; b++) g_mi[b*Hh + o] = acc[b] + bias;
    }
}

// ---------------- K9: y = x + gate*mi; LayerNorm (warp per row, no barriers) ----------------
__global__ void __launch_bounds__(256) k_final(const float* __restrict__ x,
                                               const float* __restrict__ gamma,
                                               const float* __restrict__ beta,
                                               float* __restrict__ out) {
    int lane = threadIdx.x & 31, warp = threadIdx.x >> 5;
    int row = blockIdx.x*8 + warp;              // 2048 blocks * 8 warps = 16384 rows
    int b = row >> 11;
    const float4* xr = (const float4*)x + (size_t)row*512;
    const float4* gp = (const float4*)g_gate + b*512;
    const float4* mp = (const float4*)g_mi   + b*512;
    float4* orow = (float4*)out + (size_t)row*512;
    float4 y[16];
    float s = 0.f, ss = 0.f;
#pragma unroll
    for (int j = 0; j < 16; j++) {
        int c = j*32 + lane;
        float4 xv = __ldcs(xr + c);
        float4 g  = __ldg(gp + c);
        float4 m  = __ldg(mp + c);
        float4 yv;
        yv.x = xv.x + g.x*m.x; yv.y = xv.y + g.y*m.y;
        yv.z = xv.z + g.z*m.z; yv.w = xv.w + g.w*m.w;
        y[j] = yv;
        s  += yv.x + yv.y + yv.z + yv.w;
        ss += yv.x*yv.x + yv.y*yv.y + yv.z*yv.z + yv.w*yv.w;
    }
#pragma unroll
    for (int off = 16; off; off >>= 1) {
        s  += __shfl_xor_sync(0xffffffffu, s,  off);
        ss += __shfl_xor_sync(0xffffffffu, ss, off);
    }
    float mu  = s  * (1.0f/2048.0f);
    float var = ss * (1.0f/2048.0f) - mu*mu;
    float rstd = rsqrtf(var + 1e-5f);
#pragma unroll
    for (int j = 0; j < 16; j++) {
        int c = j*32 + lane;
        float4 gm = __ldg((const float4*)gamma + c);
        float4 be = __ldg((const float4*)beta  + c);
        float4 yv = y[j], o;
        o.x = (yv.x - mu)*rstd*gm.x + be.x;
        o.y = (yv.y - mu)*rstd*gm.y + be.y;
        o.z = (yv.z - mu)*rstd*gm.z + be.z;
        o.w = (yv.w - mu)*rstd*gm.w + be.w;
        orow[c] = o;
    }
}

// ---------------- launch ----------------
extern "C" void kernel_launch(void* const* d_in, const int* in_sizes, int n_in,
                              void* d_out, int out_size) {
    const float* x     = (const float*)d_in[0];
    const float* keys  = (const float*)d_in[1];
    const float* conf  = (const float*)d_in[2];
    const float* Wq    = (const float*)d_in[3];
    const float* bq    = (const float*)d_in[4];
    const float* Wk    = (const float*)d_in[5];
    const float* bk    = (const float*)d_in[6];
    const float* Wg    = (const float*)d_in[7];
    const float* bg    = (const float*)d_in[8];
    const float* Wm1   = (const float*)d_in[9];
    const float* bm1   = (const float*)d_in[10];
    const float* Wm2   = (const float*)d_in[11];
    const float* bm2   = (const float*)d_in[12];
    const float* gamma = (const float*)d_in[13];
    const float* beta  = (const float*)d_in[14];
    float* out = (float*)d_out;

    k_partial <<<dim3(16,32), 256>>>(x);             // 0
    k_qmean   <<<16, 256>>>();                       // 1
    k_qproj   <<<64, 256>>>(Wq, bq);                 // 2
    k_qk      <<<64, 256>>>(Wk, bk);                 // 3
    k_scores  <<<3125, 128>>>(keys, conf);           // 4
    k_topk1   <<<dim3(NCH, Bb), 256>>>();            // 5
    k_topk2gi <<<8, 256>>>(keys);                    // 6
    k_mlp1    <<<512, 256>>>(Wg, bg, Wm1, bm1);      // 7
    k_mi      <<<256, 256>>>(Wm2, bm2);              // 8
    k_final   <<<2048, 256>>>(x, gamma, beta, out);  // 9
}

// round 11
// speedup vs baseline: 1.8238x; 1.0108x over previous
#include <cuda_runtime.h>
#include <math.h>

#define Bb   8
#define Tt   2048
#define Hh   2048
#define Nn   100000
#define Pp   512
#define TOPK 10
#define NCH  40
#define CHSZ 2500

typedef unsigned long long ull;

// ---------------- scratch ----------------
__device__ float g_part[Bb*32*Hh];
__device__ float g_query[Bb*Hh];
__device__ float g_q[Bb*Pp];
__device__ float g_sbk[Bb];
__device__ float g_qkD[Bb*Hh];
__device__ float g_scores[Bb*Nn];
__device__ float g_cval[Bb*NCH*TOPK];
__device__ int   g_cidx[Bb*NCH*TOPK];
__device__ float g_gi[Bb*2*Hh];
__device__ float g_gate[Bb*Hh];
__device__ float g_h1[Bb*Hh];
__device__ float g_mi[Bb*Hh];

// ---------------- f32x2 helpers ----------------
__device__ __forceinline__ ull pk2(float a, float b) {
    ull r; asm("mov.b64 %0,{%1,%2};" : "=l"(r) : "f"(a), "f"(b)); return r;
}
__device__ __forceinline__ void up2(ull v, float& a, float& b) {
    asm("mov.b64 {%0,%1},%2;" : "=f"(a), "=f"(b) : "l"(v));
}
__device__ __forceinline__ ull fma2(ull a, ull b, ull c) {
    ull d; asm("fma.rn.f32x2 %0,%1,%2,%3;" : "=l"(d) : "l"(a), "l"(b), "l"(c)); return d;
}

// ---------------- K0: partial sums over T ----------------
__global__ void __launch_bounds__(256) k_partial(const float* __restrict__ x) {
    int b = blockIdx.x >> 1, hseg = blockIdx.x & 1, chunk = blockIdx.y;
    const float4* xp = (const float4*)x
        + ((size_t)(b*Tt + chunk*64) * Hh + hseg*1024) / 4 + threadIdx.x;
    float4 s = make_float4(0.f,0.f,0.f,0.f);
#pragma unroll 8
    for (int t = 0; t < 64; t++) {
        float4 v = __ldcs(xp + (size_t)t * (Hh/4));
        s.x += v.x; s.y += v.y; s.z += v.z; s.w += v.w;
    }
    ((float4*)g_part)[(b*32 + chunk)*(Hh/4) + hseg*256 + threadIdx.x] = s;
}

// ---------------- K1: query mean (16 blocks) ----------------
__global__ void __launch_bounds__(256) k_qmean() {
    int id = blockIdx.x*256 + threadIdx.x;   // 4096 = B*H/4
    int b = id >> 9, h4 = id & 511;
    float4 s = make_float4(0.f,0.f,0.f,0.f);
#pragma unroll
    for (int c = 0; c < 32; c++) {
        float4 v = ((const float4*)g_part)[(b*32 + c)*512 + h4];
        s.x += v.x; s.y += v.y; s.z += v.z; s.w += v.w;
    }
    const float inv = 1.0f / (float)Tt;
    s.x *= inv; s.y *= inv; s.z *= inv; s.w *= inv;
    ((float4*)g_query)[b*512 + h4] = s;
}

// ---------------- K2: q = query @ Wq^T + bq  (explicit MLP batching) ----------------
__global__ void __launch_bounds__(256) k_qproj(const float* __restrict__ Wq,
                                               const float* __restrict__ bq) {
    int lane = threadIdx.x & 31, warp = threadIdx.x >> 5;
    int o = blockIdx.x*8 + warp;
    const float4* w  = (const float4*)Wq + (size_t)o*512;
    const float4* gq = (const float4*)g_query;
    float acc[8] = {0.f,0.f,0.f,0.f,0.f,0.f,0.f,0.f};
    for (int j0 = 0; j0 < 16; j0 += 4) {
        float4 wb[4];
#pragma unroll
        for (int jj = 0; jj < 4; jj++)
            wb[jj] = __ldg(w + (j0 + jj)*32 + lane);
#pragma unroll
        for (int jj = 0; jj < 4; jj++) {
            int i = (j0 + jj)*32 + lane;
            float4 a = wb[jj];
#pragma unroll
            for (int b = 0; b < 8; b++) {
                float4 c = __ldg(gq + b*512 + i);
                acc[b] += a.x*c.x + a.y*c.y + a.z*c.z + a.w*c.w;
            }
        }
    }
#pragma unroll
    for (int off = 16; off; off >>= 1)
#pragma unroll
        for (int b = 0; b < 8; b++) acc[b] += __shfl_xor_sync(0xffffffffu, acc[b], off);
    if (lane == 0) {
        float bias = __ldg(&bq[o]);
#pragma unroll
        for (int b = 0; b < 8; b++) g_q[b*Pp + o] = acc[b] + bias;
    }
}

// ---------------- K3: qk = q @ Wk → qkD; sbk fused (64 blocks x 512 thr, forced MLP=8) ----------------
__global__ void __launch_bounds__(512) k_qk(const float* __restrict__ Wk,
                                            const float* __restrict__ bk) {
    __shared__ float qsm[Pp*Bb];        // [p][b] packed, 16KB
    __shared__ float red[16*32*8];      // [ps][lh][b], 16KB
    int tid = threadIdx.x;
    for (int j = tid; j < Bb*Pp; j += 512) {
        int b = j >> 9, p = j & 511;
        qsm[p*8 + b] = g_q[j];
    }
    __syncthreads();
    int lane = tid & 31, ps = tid >> 5;          // ps 0..15
    // sbk: block 0, warps 0..7 (one batch each)
    if (blockIdx.x == 0 && ps < 8) {
        float s = 0.f;
        for (int p = lane; p < Pp; p += 32) s += qsm[p*8 + ps] * __ldg(&bk[p]);
#pragma unroll
        for (int off = 16; off; off >>= 1) s += __shfl_xor_sync(0xffffffffu, s, off);
        if (lane == 0) g_sbk[ps] = s;
    }
    int h = blockIdx.x*32 + lane;
    int p0 = ps*32;                               // 32 p per warp
    float acc[8] = {0.f,0.f,0.f,0.f,0.f,0.f,0.f,0.f};
#pragma unroll
    for (int j0 = 0; j0 < 32; j0 += 8) {
        float wbuf[8];
#pragma unroll
        for (int jj = 0; jj < 8; jj++)            // 8 independent DRAM loads in flight
            wbuf[jj] = __ldg(&Wk[(size_t)(p0 + j0 + jj)*Hh + h]);
#pragma unroll
        for (int jj = 0; jj < 8; jj++) {
            const float4* qp = (const float4*)&qsm[(p0 + j0 + jj)*8];
            float4 qA = qp[0], qB = qp[1];
            float w = wbuf[jj];
            acc[0] += qA.x*w; acc[1] += qA.y*w; acc[2] += qA.z*w; acc[3] += qA.w*w;
            acc[4] += qB.x*w; acc[5] += qB.y*w; acc[6] += qB.z*w; acc[7] += qB.w*w;
        }
    }
#pragma unroll
    for (int b = 0; b < 8; b++) red[(ps*32 + lane)*8 + b] = acc[b];
    __syncthreads();
    // reduce over 16 p-splits: first 256 threads, one (lh,b) each
    if (tid < 256) {
        int lh = tid >> 3, b = tid & 7;
        float s = 0.f;
#pragma unroll
        for (int p2 = 0; p2 < 16; p2++) s += red[(p2*32 + lh)*8 + b];
        int hg = blockIdx.x*32 + lh;
        int c = hg >> 2, i = c >> 5, l = c & 31, hh = hg & 3;
        g_qkD[((i*8 + 2*hh + (b >> 2))*32 + l)*4 + (b & 3)] = s;
    }
}

// ---------------- K4: scores (software-pipelined, 8 rows/warp) ----------------
__device__ __forceinline__ void score_step(const float4 kv[8], const float4* __restrict__ qkD4,
                                           int i, int lane, ull acc[8][4]) {
#pragma unroll
    for (int hh = 0; hh < 4; hh++) {
        ull kd[8];
#pragma unroll
        for (int r = 0; r < 8; r++) {
            float cc = (hh == 0) ? kv[r].x : (hh == 1) ? kv[r].y
                     : (hh == 2) ? kv[r].z : kv[r].w;
            kd[r] = pk2(cc, cc);
        }
#pragma unroll
        for (int s = 0; s < 2; s++) {
            float4 qv = __ldg(&qkD4[(i*8 + hh*2 + s)*32 + lane]);
            ull qlo = pk2(qv.x, qv.y), qhi = pk2(qv.z, qv.w);
#pragma unroll
            for (int r = 0; r < 8; r++) {
                acc[r][2*s]   = fma2(kd[r], qlo, acc[r][2*s]);
                acc[r][2*s+1] = fma2(kd[r], qhi, acc[r][2*s+1]);
            }
        }
    }
}

__global__ void __launch_bounds__(128) k_scores(const float* __restrict__ keys,
                                                const float* __restrict__ conf) {
    const int lane = threadIdx.x & 31;
    const int warp = threadIdx.x >> 5;
    const int n0 = blockIdx.x*32 + warp*8;
    const float4* __restrict__ qkD4 = (const float4*)g_qkD;
    const float4* k0 = (const float4*)keys + (size_t)n0 * (Hh/4);
    float sbk[8];
#pragma unroll
    for (int bb = 0; bb < 8; bb++) sbk[bb] = __ldg(&g_sbk[bb]);
    ull acc[8][4];
#pragma unroll
    for (int r = 0; r < 8; r++)
#pragma unroll
        for (int j = 0; j < 4; j++) acc[r][j] = 0ull;
    float4 kvA[8], kvB[8];
#pragma unroll
    for (int r = 0; r < 8; r++)
        kvA[r] = __ldcg(k0 + (size_t)r*(Hh/4) + lane);            // i=0
    for (int i = 0; i < 16; i += 2) {
#pragma unroll
        for (int r = 0; r < 8; r++)                               // prefetch i+1
            kvB[r] = __ldcg(k0 + (size_t)r*(Hh/4) + (i+1)*32 + lane);
        score_step(kvA, qkD4, i, lane, acc);
        if (i + 2 < 16) {
#pragma unroll
            for (int r = 0; r < 8; r++)                           // prefetch i+2
                kvA[r] = __ldcg(k0 + (size_t)r*(Hh/4) + (i+2)*32 + lane);
        }
        score_step(kvB, qkD4, i+1, lane, acc);
    }
#pragma unroll
    for (int r = 0; r < 8; r++) {
        float a[8];
#pragma unroll
        for (int j = 0; j < 4; j++) up2(acc[r][j], a[2*j], a[2*j+1]);
#pragma unroll
        for (int off = 16; off; off >>= 1)
#pragma unroll
            for (int bb = 0; bb < 8; bb++)
                a[bb] += __shfl_xor_sync(0xffffffffu, a[bb], off);
        if (lane == 0) {
            int n = n0 + r;
            float cf = __ldg(&conf[n]);
#pragma unroll
            for (int bb = 0; bb < 8; bb++)
                g_scores[(size_t)bb*Nn + n] = (a[bb] + sbk[bb]) * cf;
        }
    }
}

// ---------------- K5: top-k stage 1 ----------------
__global__ void __launch_bounds__(256) k_topk1() {
    int b = blockIdx.y, c = blockIdx.x, tid = threadIdx.x;
    int nbase = c * CHSZ;
    float v[TOPK]; int ix[TOPK];
#pragma unroll
    for (int j = 0; j < TOPK; j++) { v[j] = -3.4e38f; ix[j] = 0x7fffffff; }
    const float* sc = g_scores + (size_t)b*Nn + nbase;
    for (int n = tid; n < CHSZ; n += 256) {
        float s = sc[n];
        if (s > v[TOPK-1]) {
            v[TOPK-1] = s; ix[TOPK-1] = nbase + n;
#pragma unroll
            for (int j = TOPK-1; j > 0; j--) {
                bool sw = (v[j] > v[j-1]) || (v[j] == v[j-1] && ix[j] < ix[j-1]);
                if (sw) {
                    float tv = v[j]; v[j] = v[j-1]; v[j-1] = tv;
                    int   ti = ix[j]; ix[j] = ix[j-1]; ix[j-1] = ti;
                }
            }
        }
    }
    __shared__ float sv[256*TOPK];
    __shared__ int   si[256*TOPK];
    __shared__ float rv[256]; __shared__ int ri[256]; __shared__ int rp[256];
#pragma unroll
    for (int j = 0; j < TOPK; j++) { sv[tid*TOPK + j] = v[j]; si[tid*TOPK + j] = ix[j]; }
    __syncthreads();
    for (int k = 0; k < TOPK; k++) {
        float bv = -3.4e38f; int bi = 0x7fffffff, bp = 0;
        for (int j = tid; j < 256*TOPK; j += 256) {
            float cv = sv[j]; int ci = si[j];
            if (cv > bv || (cv == bv && ci < bi)) { bv = cv; bi = ci; bp = j; }
        }
        rv[tid] = bv; ri[tid] = bi; rp[tid] = bp;
        __syncthreads();
        for (int st = 128; st > 0; st >>= 1) {
            if (tid < st) {
                float cv = rv[tid+st]; int ci = ri[tid+st];
                if (cv > rv[tid] || (cv == rv[tid] && ci < ri[tid])) {
                    rv[tid] = cv; ri[tid] = ci; rp[tid] = rp[tid+st];
                }
            }
            __syncthreads();
        }
        if (tid == 0) {
            g_cval[(b*NCH + c)*TOPK + k] = rv[0];
            g_cidx[(b*NCH + c)*TOPK + k] = ri[0];
            sv[rp[0]] = -3.4e38f;
        }
        __syncthreads();
    }
}

// ---------------- K6: top-k stage 2 + gather mean + gate_input ----------------
__global__ void __launch_bounds__(256) k_topk2gi(const float* __restrict__ keys) {
    int b = blockIdx.x, tid = threadIdx.x;
    const int NC = NCH*TOPK;
    __shared__ float cv[NC]; __shared__ int ci[NC];
    __shared__ float rv[256]; __shared__ int ri[256]; __shared__ int rp[256];
    __shared__ int topi[TOPK];
    for (int j = tid; j < NC; j += 256) {
        cv[j] = g_cval[b*NC + j]; ci[j] = g_cidx[b*NC + j];
    }
    __syncthreads();
    for (int k = 0; k < TOPK; k++) {
        float bv = -3.4e38f; int bi = 0x7fffffff, bp = 0;
        for (int j = tid; j < NC; j += 256) {
            float vv = cv[j]; int ii = ci[j];
            if (vv > bv || (vv == bv && ii < bi)) { bv = vv; bi = ii; bp = j; }
        }
        rv[tid] = bv; ri[tid] = bi; rp[tid] = bp;
        __syncthreads();
        for (int st = 128; st > 0; st >>= 1) {
            if (tid < st) {
                float vv = rv[tid+st]; int ii = ri[tid+st];
                if (vv > rv[tid] || (vv == rv[tid] && ii < ri[tid])) {
                    rv[tid] = vv; ri[tid] = ii; rp[tid] = rp[tid+st];
                }
            }
            __syncthreads();
        }
        if (tid == 0) { topi[k] = ri[0]; cv[rp[0]] = -3.4e38f; }
        __syncthreads();
    }
    int idx[TOPK];
#pragma unroll
    for (int j = 0; j < TOPK; j++) idx[j] = topi[j];
    for (int h4 = tid; h4 < 512; h4 += 256) {
        ((float4*)g_gi)[b*1024 + h4] = ((const float4*)g_query)[b*512 + h4];
        float4 s = make_float4(0.f,0.f,0.f,0.f);
#pragma unroll
        for (int j = 0; j < TOPK; j++) {
            float4 kv = __ldg((const float4*)keys + (size_t)idx[j]*(Hh/4) + h4);
            s.x += kv.x; s.y += kv.y; s.z += kv.z; s.w += kv.w;
        }
        const float inv = 1.0f / (float)TOPK;
        s.x *= inv; s.y *= inv; s.z *= inv; s.w *= inv;
        ((float4*)g_gi)[b*1024 + 512 + h4] = s;
    }
}

// ---------------- K7: gate/h1 ----------------
__global__ void __launch_bounds__(256) k_mlp1(const float* __restrict__ Wg,
                                              const float* __restrict__ bg,
                                              const float* __restrict__ Wm1,
                                              const float* __restrict__ bm1) {
    int lane = threadIdx.x & 31, warp = threadIdx.x >> 5;
    int wg = blockIdx.x*8 + warp;
    int which = wg >> 11, o = wg & 2047;
    const float4* W = (const float4*)(which ? Wm1 : Wg) + (size_t)o*1024;
    float acc[8] = {0.f,0.f,0.f,0.f,0.f,0.f,0.f,0.f};
    for (int i = lane; i < 1024; i += 32) {
        float4 w = __ldcs(W + i);
#pragma unroll
        for (int b = 0; b < 8; b++) {
            float4 g = __ldg((const float4*)g_gi + b*1024 + i);
            acc[b] += w.x*g.x + w.y*g.y + w.z*g.z + w.w*g.w;
        }
    }
#pragma unroll
    for (int off = 16; off; off >>= 1)
#pragma unroll
        for (int b = 0; b < 8; b++) acc[b] += __shfl_xor_sync(0xffffffffu, acc[b], off);
    if (lane == 0) {
        float bias = which ? bm1[o] : bg[o];
#pragma unroll
        for (int b = 0; b < 8; b++) {
            float z = acc[b] + bias;
            if (which) g_h1[b*Hh + o] = 0.5f*z*(1.0f + erff(z*0.70710678118654752440f));
            else       g_gate[b*Hh + o] = 1.0f / (1.0f + expf(-z));
        }
    }
}

// ---------------- K8: mem_integrated ----------------
__global__ void __launch_bounds__(256) k_mi(const float* __restrict__ Wm2,
                                            const float* __restrict__ bm2) {
    int lane = threadIdx.x & 31, warp = threadIdx.x >> 5;
    int o = blockIdx.x*8 + warp;
    const float4* W = (const float4*)Wm2 + (size_t)o*512;
    float acc[8] = {0.f,0.f,0.f,0.f,0.f,0.f,0.f,0.f};
    for (int i = lane; i < 512; i += 32) {
        float4 w = __ldcs(W + i);
#pragma unroll
        for (int b = 0; b < 8; b++) {
            float4 g = __ldg((const float4*)g_h1 + b*512 + i);
            acc[b] += w.x*g.x + w.y*g.y + w.z*g.z + w.w*g.w;
        }
    }
#pragma unroll
    for (int off = 16; off; off >>= 1)
#pragma unroll
        for (int b = 0; b < 8; b++) acc[b] += __shfl_xor_sync(0xffffffffu, acc[b], off);
    if (lane == 0) {
        float bias = bm2[o];
#pragma unroll
        for (int b = 0; b < 8; b++) g_mi[b*Hh + o] = acc[b] + bias;
    }
}

// ---------------- K9: y = x + gate*mi; LayerNorm (warp per row, no barriers) ----------------
__global__ void __launch_bounds__(256) k_final(const float* __restrict__ x,
                                               const float* __restrict__ gamma,
                                               const float* __restrict__ beta,
                                               float* __restrict__ out) {
    int lane = threadIdx.x & 31, warp = threadIdx.x >> 5;
    int row = blockIdx.x*8 + warp;              // 2048 blocks * 8 warps = 16384 rows
    int b = row >> 11;
    const float4* xr = (const float4*)x + (size_t)row*512;
    const float4* gp = (const float4*)g_gate + b*512;
    const float4* mp = (const float4*)g_mi   + b*512;
    float4* orow = (float4*)out + (size_t)row*512;
    float4 y[16];
    float s = 0.f, ss = 0.f;
#pragma unroll
    for (int j = 0; j < 16; j++) {
        int c = j*32 + lane;
        float4 xv = __ldcs(xr + c);
        float4 g  = __ldg(gp + c);
        float4 m  = __ldg(mp + c);
        float4 yv;
        yv.x = xv.x + g.x*m.x; yv.y = xv.y + g.y*m.y;
        yv.z = xv.z + g.z*m.z; yv.w = xv.w + g.w*m.w;
        y[j] = yv;
        s  += yv.x + yv.y + yv.z + yv.w;
        ss += yv.x*yv.x + yv.y*yv.y + yv.z*yv.z + yv.w*yv.w;
    }
#pragma unroll
    for (int off = 16; off; off >>= 1) {
        s  += __shfl_xor_sync(0xffffffffu, s,  off);
        ss += __shfl_xor_sync(0xffffffffu, ss, off);
    }
    float mu  = s  * (1.0f/2048.0f);
    float var = ss * (1.0f/2048.0f) - mu*mu;
    float rstd = rsqrtf(var + 1e-5f);
#pragma unroll
    for (int j = 0; j < 16; j++) {
        int c = j*32 + lane;
        float4 gm = __ldg((const float4*)gamma + c);
        float4 be = __ldg((const float4*)beta  + c);
        float4 yv = y[j], o;
        o.x = (yv.x - mu)*rstd*gm.x + be.x;
        o.y = (yv.y - mu)*rstd*gm.y + be.y;
        o.z = (yv.z - mu)*rstd*gm.z + be.z;
        o.w = (yv.w - mu)*rstd*gm.w + be.w;
        orow[c] = o;
    }
}

// ---------------- launch ----------------
extern "C" void kernel_launch(void* const* d_in, const int* in_sizes, int n_in,
                              void* d_out, int out_size) {
    const float* x     = (const float*)d_in[0];
    const float* keys  = (const float*)d_in[1];
    const float* conf  = (const float*)d_in[2];
    const float* Wq    = (const float*)d_in[3];
    const float* bq    = (const float*)d_in[4];
    const float* Wk    = (const float*)d_in[5];
    const float* bk    = (const float*)d_in[6];
    const float* Wg    = (const float*)d_in[7];
    const float* bg    = (const float*)d_in[8];
    const float* Wm1   = (const float*)d_in[9];
    const float* bm1   = (const float*)d_in[10];
    const float* Wm2   = (const float*)d_in[11];
    const float* bm2   = (const float*)d_in[12];
    const float* gamma = (const float*)d_in[13];
    const float* beta  = (const float*)d_in[14];
    float* out = (float*)d_out;

    k_partial <<<dim3(16,32), 256>>>(x);             // 0
    k_qmean   <<<16, 256>>>();                       // 1
    k_qproj   <<<64, 256>>>(Wq, bq);                 // 2
    k_qk      <<<64, 512>>>(Wk, bk);                 // 3
    k_scores  <<<3125, 128>>>(keys, conf);           // 4
    k_topk1   <<<dim3(NCH, Bb), 256>>>();            // 5
    k_topk2gi <<<8, 256>>>(keys);                    // 6
    k_mlp1    <<<512, 256>>>(Wg, bg, Wm1, bm1);      // 7
    k_mi      <<<256, 256>>>(Wm2, bm2);              // 8
    k_final   <<<2048, 256>>>(x, gamma, beta, out);  // 9
}